// round 16
// baseline (speedup 1.0000x reference)
#include <cuda_runtime.h>
#include <cuda_bf16.h>
#include <cuda_fp8.h>
#include <cstdint>

#define BATCH 4096
#define NVIEW 2
#define DIM   512
#define NTOT  8192
#define NCLS  1000

#define C_EXP  20.60992915555662f   // log2(e)/0.07
#define INV_T  14.285714285714286f  // 1/0.07
#define EBIAS  10.0f
#define ESCALE 1024.0f              // 2^EBIAS

#define NTILES_TOTAL 2080
#define NCTA 148

// ---------------- smem layout (bytes) ----------------
#define A_STRIDE   528                 // 512 fp8 + 16 pad per row -> conflict-free ldmatrix
#define TILE_BYTES (128 * A_STRIDE)    // 67584
#define OFF_A      0
#define OFF_B      TILE_BYTES          // two full-K B stages
#define OFF_RED    (OFF_B + 2 * TILE_BYTES)   // 202752
#define OFF_MBAR   (OFF_RED + 4 * 128 * 4)    // 204800
#define SMEM_TOTAL (OFF_MBAR + 16)            // 204816

// ---------------- scratch ----------------
__device__ __align__(16) uint8_t g_A8[(size_t)NTOT * DIM];
__device__ __align__(16) float   g_Ssum[NCLS * DIM];
__device__ float g_Z[NTOT];
__device__ float g_sum;
__device__ int   g_cnt[NCLS];
__device__ unsigned g_done;

// ---------------- PTX helpers ----------------
__device__ __forceinline__ void ldm4(uint32_t r[4], uint32_t addr) {
    asm volatile("ldmatrix.sync.aligned.m8n8.x4.shared.b16 {%0,%1,%2,%3}, [%4];"
        : "=r"(r[0]), "=r"(r[1]), "=r"(r[2]), "=r"(r[3]) : "r"(addr));
}
__device__ __forceinline__ void qmma(float c[4], const uint32_t a[4], const uint32_t b[2]) {
    asm volatile("mma.sync.aligned.m16n8k32.row.col.f32.e4m3.e4m3.f32 "
        "{%0,%1,%2,%3}, {%4,%5,%6,%7}, {%8,%9}, {%0,%1,%2,%3};"
        : "+f"(c[0]), "+f"(c[1]), "+f"(c[2]), "+f"(c[3])
        : "r"(a[0]), "r"(a[1]), "r"(a[2]), "r"(a[3]), "r"(b[0]), "r"(b[1]));
}
__device__ __forceinline__ uint32_t smem_u32(const void* p) {
    uint32_t a;
    asm("{ .reg .u64 t; cvta.to.shared.u64 t, %1; cvt.u32.u64 %0, t; }" : "=r"(a) : "l"(p));
    return a;
}
__device__ __forceinline__ void bulk_cp(uint32_t dst, const void* src, uint32_t bytes, uint32_t mbar) {
    asm volatile("cp.async.bulk.shared::cta.global.mbarrier::complete_tx::bytes [%0], [%1], %2, [%3];"
        :: "r"(dst), "l"(src), "r"(bytes), "r"(mbar) : "memory");
}
__device__ __forceinline__ void bulk_red_add_f32(void* gdst, uint32_t ssrc, uint32_t bytes) {
    asm volatile("cp.reduce.async.bulk.global.shared::cta.bulk_group.add.f32 [%0], [%1], %2;"
        :: "l"(gdst), "r"(ssrc), "r"(bytes) : "memory");
}
__device__ __forceinline__ void bulk_commit() {
    asm volatile("cp.async.bulk.commit_group;" ::: "memory");
}
__device__ __forceinline__ void bulk_wait0() {
    asm volatile("cp.async.bulk.wait_group 0;" ::: "memory");
}
__device__ __forceinline__ void mbar_init(uint32_t mbar, uint32_t cnt) {
    asm volatile("mbarrier.init.shared.b64 [%0], %1;" :: "r"(mbar), "r"(cnt) : "memory");
}
__device__ __forceinline__ void mbar_expect(uint32_t mbar, uint32_t bytes) {
    asm volatile("mbarrier.arrive.expect_tx.shared.b64 _, [%0], %1;" :: "r"(mbar), "r"(bytes) : "memory");
}
__device__ __forceinline__ void mbar_wait(uint32_t mbar, uint32_t parity) {
    uint32_t done;
    asm volatile("{ .reg .pred p; mbarrier.try_wait.parity.acquire.cta.shared::cta.b64 p, [%1], %2; selp.b32 %0, 1, 0, p; }"
        : "=r"(done) : "r"(mbar), "r"(parity) : "memory");
    if (!done) {
        asm volatile("{ .reg .pred P1;\n"
            "W_%=: mbarrier.try_wait.parity.acquire.cta.shared::cta.b64 P1, [%0], %1, 0x989680;\n"
            "@P1 bra.uni D_%=;\n bra.uni W_%=;\n D_%=: }"
            :: "r"(mbar), "r"(parity) : "memory");
    }
}
__device__ __forceinline__ uint32_t pack_h2(float lo, float hi) {
    uint32_t h;
    asm("cvt.rn.f16x2.f32 %0, %1, %2;" : "=r"(h) : "f"(hi), "f"(lo));
    return h;
}
__device__ __forceinline__ uint32_t ex2_h2(uint32_t x) {
    uint32_t e;
    asm("ex2.approx.f16x2 %0, %1;" : "=r"(e) : "r"(x));
    return e;
}
__device__ __forceinline__ uint32_t hadd2(uint32_t a, uint32_t b) {
    uint32_t d;
    asm("add.rn.f16x2 %0, %1, %2;" : "=r"(d) : "r"(a), "r"(b));
    return d;
}
__device__ __forceinline__ float2 h2_to_f2(uint32_t h) {
    float lo, hi;
    asm("{ .reg .f16 l, hh; mov.b32 {l, hh}, %2; cvt.f32.f16 %0, l; cvt.f32.f16 %1, hh; }"
        : "=f"(lo), "=f"(hi) : "r"(h));
    return make_float2(lo, hi);
}
// two fp8 (e4m3) packed in low 16 bits -> float2
__device__ __forceinline__ float2 fp8x2_to_f2(uint32_t packed16) {
    uint32_t h;
    asm("cvt.rn.f16x2.e4m3x2 %0, %1;" : "=r"(h) : "h"((unsigned short)packed16));
    return h2_to_f2(h);
}
// flattened upper-triangle tile list: iblk<32 -> c in [0,33), else c in [0,32)
__device__ __forceinline__ void decode_tile(int g, int& ib, int& c) {
    if (g < 1056) { ib = g / 33; c = g - ib * 33; }
    else { int h = g - 1056; ib = 32 + (h >> 5); c = h & 31; }
}

// ------------------------- kernel 1: normalize both views per warp -> fp8 + one bulk-reduce per sample -------------------------
__global__ void norm_kernel(const float* __restrict__ feats, const int* __restrict__ labels) {
    __shared__ float stage[8][DIM];
    const int warp = threadIdx.x >> 5, lane = threadIdx.x & 31;
    const int b = blockIdx.x * 8 + warp;          // sample 0..4095
    const int cls = labels[b];
    const float4* src0 = reinterpret_cast<const float4*>(feats + (size_t)(b * NVIEW + 0) * DIM);
    const float4* src1 = reinterpret_cast<const float4*>(feats + (size_t)(b * NVIEW + 1) * DIM);
    float4 f0[4], f1[4];
    float ss0 = 0.f, ss1 = 0.f;
#pragma unroll
    for (int q = 0; q < 4; q++) {
        f0[q] = src0[lane + 32 * q];
        f1[q] = src1[lane + 32 * q];
        ss0 += f0[q].x * f0[q].x + f0[q].y * f0[q].y + f0[q].z * f0[q].z + f0[q].w * f0[q].w;
        ss1 += f1[q].x * f1[q].x + f1[q].y * f1[q].y + f1[q].z * f1[q].z + f1[q].w * f1[q].w;
    }
#pragma unroll
    for (int o = 16; o; o >>= 1) {
        ss0 += __shfl_xor_sync(0xffffffffu, ss0, o);
        ss1 += __shfl_xor_sync(0xffffffffu, ss1, o);
    }
    float sc0 = 1.0f / fmaxf(sqrtf(ss0), 1e-8f);
    float sc1 = 1.0f / fmaxf(sqrtf(ss1), 1e-8f);
    if (lane == 0) {
        g_Z[b] = 0.f;
        g_Z[BATCH + b] = 0.f;
        atomicAdd(&g_cnt[cls], 1);
    }
    uint32_t* e0 = reinterpret_cast<uint32_t*>(g_A8 + (size_t)b * DIM);
    uint32_t* e1 = reinterpret_cast<uint32_t*>(g_A8 + (size_t)(BATCH + b) * DIM);
    float4* srow = reinterpret_cast<float4*>(stage[warp]);
#pragma unroll
    for (int q = 0; q < 4; q++) {
        float x0 = f0[q].x * sc0, y0 = f0[q].y * sc0, z0 = f0[q].z * sc0, w0 = f0[q].w * sc0;
        float x1 = f1[q].x * sc1, y1 = f1[q].y * sc1, z1 = f1[q].z * sc1, w1 = f1[q].w * sc1;
        __nv_fp8x2_storage_t l0 = __nv_cvt_float2_to_fp8x2(make_float2(x0, y0), __NV_SATFINITE, __NV_E4M3);
        __nv_fp8x2_storage_t h0 = __nv_cvt_float2_to_fp8x2(make_float2(z0, w0), __NV_SATFINITE, __NV_E4M3);
        __nv_fp8x2_storage_t l1 = __nv_cvt_float2_to_fp8x2(make_float2(x1, y1), __NV_SATFINITE, __NV_E4M3);
        __nv_fp8x2_storage_t h1 = __nv_cvt_float2_to_fp8x2(make_float2(z1, w1), __NV_SATFINITE, __NV_E4M3);
        e0[lane + 32 * q] = (uint32_t)l0 | ((uint32_t)h0 << 16);
        e1[lane + 32 * q] = (uint32_t)l1 | ((uint32_t)h1 << 16);
        srow[lane + 32 * q] = make_float4(x0 + x1, y0 + y1, z0 + z1, w0 + w1);
    }
    asm volatile("fence.proxy.async.shared::cta;" ::: "memory");
    __syncwarp();
    if (lane == 0) {
        bulk_red_add_f32(g_Ssum + (size_t)cls * DIM, smem_u32(stage[warp]), DIM * 4);
        bulk_commit();
        bulk_wait0();
    }
}

// ------------------------- kernel 2: fp8 GEMM upper triangle, flat 148-CTA schedule (verified) -------------------------
__global__ void __launch_bounds__(512, 1) supcon_main() {
    extern __shared__ char smem[];
    const int t = threadIdx.x, lane = t & 31, wid = t >> 5;
    const int warp_m = wid >> 2, warp_n = wid & 3;      // 4 x 4 warps, 32x32 tiles
    const int g0 = (NTILES_TOTAL * blockIdx.x) / NCTA;
    const int g1 = (NTILES_TOTAL * (blockIdx.x + 1)) / NCTA;
    const uint32_t sbase = smem_u32(smem);
    const uint32_t mb = sbase + OFF_MBAR;
    float* red = reinterpret_cast<float*>(smem + OFF_RED);   // [4][128]

    if (t == 0) { mbar_init(mb, 1); mbar_init(mb + 8, 1); }

    int ib0, c0;
    decode_tile(g0, ib0, c0);

    // load A tile for first iblk
    for (int f = t; f < 4096; f += 512) {
        int row = f >> 5, seg = f & 31;
        uint4 v = *reinterpret_cast<const uint4*>(g_A8 + (size_t)(ib0 * 128 + row) * DIM + seg * 16);
        *reinterpret_cast<uint4*>(smem + OFF_A + row * A_STRIDE + seg * 16) = v;
    }
    __syncthreads();   // A visible + mbars initialized

    // prologue: bulk-copy B tile of g0 into buf 0
    {
        const int jb = (ib0 + c0) & 63;
        if (t == 0) mbar_expect(mb, 128 * 512);
        if (t < 128)
            bulk_cp(sbase + OFF_B + t * A_STRIDE, g_A8 + (size_t)jb * (128 * DIM) + t * 512, 512, mb);
    }

    const uint32_t abase = sbase + OFF_A + (warp_m * 32 + (lane & 15)) * A_STRIDE + (lane >> 4) * 16;
    const uint32_t bb_lane = (((lane & 7) + ((lane >> 4) & 1) * 8) + warp_n * 32) * A_STRIDE + ((lane >> 3) & 1) * 16;

    float acc[2][4][4];
#pragma unroll
    for (int m = 0; m < 2; m++)
#pragma unroll
        for (int n = 0; n < 4; n++)
#pragma unroll
            for (int r = 0; r < 4; r++) acc[m][n][r] = 0.f;
    float z[4] = {0.f, 0.f, 0.f, 0.f};
    int cur_ib = ib0;

    for (int g = g0; g < g1; g++) {
        const int jl = g - g0;
        const int buf = jl & 1;
        int ib, c;
        decode_tile(g, ib, c);
        __syncthreads();                 // all warps done with buf^1 (tile g-1) and with old A
        if (g + 1 < g1) {
            int ibn, cn;
            decode_tile(g + 1, ibn, cn);
            const int jb = (ibn + cn) & 63;
            const uint32_t mbn = mb + 8 * (buf ^ 1);
            if (t == 0) mbar_expect(mbn, 128 * 512);
            if (t < 128)
                bulk_cp(sbase + OFF_B + (buf ^ 1) * TILE_BYTES + t * A_STRIDE,
                        g_A8 + (size_t)jb * (128 * DIM) + t * 512, 512, mbn);
        }
        if (ib != cur_ib) {
            // flush row sums for cur_ib
#pragma unroll
            for (int q = 0; q < 4; q++) {
                z[q] += __shfl_xor_sync(0xffffffffu, z[q], 1);
                z[q] += __shfl_xor_sync(0xffffffffu, z[q], 2);
            }
            if ((lane & 3) == 0) {
                int g4 = lane >> 2;
#pragma unroll
                for (int m = 0; m < 2; m++)
#pragma unroll
                    for (int h = 0; h < 2; h++)
                        red[warp_n * 128 + warp_m * 32 + m * 16 + h * 8 + g4] = z[2 * m + h];
            }
            __syncthreads();
            if (t < 128)
                atomicAdd(&g_Z[cur_ib * 128 + t],
                          (red[t] + red[128 + t] + red[256 + t] + red[384 + t]) * ESCALE);
            z[0] = z[1] = z[2] = z[3] = 0.f;
            // reload A for new iblk
            for (int f = t; f < 4096; f += 512) {
                int row = f >> 5, seg = f & 31;
                uint4 v = *reinterpret_cast<const uint4*>(g_A8 + (size_t)(ib * 128 + row) * DIM + seg * 16);
                *reinterpret_cast<uint4*>(smem + OFF_A + row * A_STRIDE + seg * 16) = v;
            }
            cur_ib = ib;
            __syncthreads();
        }
        mbar_wait(mb + 8 * buf, (jl >> 1) & 1);

        const uint32_t bb = sbase + OFF_B + buf * TILE_BYTES + bb_lane;
#pragma unroll
        for (int ks = 0; ks < 16; ks++) {
            const int koff = ks * 32;
            uint32_t a[2][4];
            ldm4(a[0], abase + koff);
            ldm4(a[1], abase + 16 * A_STRIDE + koff);
            uint32_t b[4][2];
#pragma unroll
            for (int p = 0; p < 2; p++) {
                uint32_t r4[4];
                ldm4(r4, bb + p * (16 * A_STRIDE) + koff);
                b[2 * p][0] = r4[0]; b[2 * p][1] = r4[1];
                b[2 * p + 1][0] = r4[2]; b[2 * p + 1][1] = r4[3];
            }
#pragma unroll
            for (int m = 0; m < 2; m++)
#pragma unroll
                for (int n = 0; n < 4; n++) qmma(acc[m][n], a[m], b[n]);
        }

        // ---- epilogue: f16x2 exp, row sums + REDG column sums ----
        {
            const int jblk = (ib + c) & 63;
            const bool dg = (c == 0);
            uint32_t zh[4] = {0, 0, 0, 0};
            uint32_t csh[4] = {0, 0, 0, 0};
#pragma unroll
            for (int m = 0; m < 2; m++)
#pragma unroll
                for (int n = 0; n < 4; n++)
#pragma unroll
                    for (int h = 0; h < 2; h++) {
                        float x0 = acc[m][n][2 * h]     * C_EXP - EBIAS;
                        float x1 = acc[m][n][2 * h + 1] * C_EXP - EBIAS;
                        if (dg) {
                            int rl = warp_m * 32 + m * 16 + h * 8 + (lane >> 2);
                            int cl0 = warp_n * 32 + n * 8 + (lane & 3) * 2;
                            if (rl == cl0)     x0 = -60.f;
                            if (rl == cl0 + 1) x1 = -60.f;
                        }
                        uint32_t e2 = ex2_h2(pack_h2(x0, x1));
                        zh[2 * m + h] = hadd2(zh[2 * m + h], e2);
                        csh[n] = hadd2(csh[n], e2);
                        acc[m][n][2 * h] = 0.f; acc[m][n][2 * h + 1] = 0.f;
                    }
#pragma unroll
            for (int q = 0; q < 4; q++) {
                float2 f = h2_to_f2(zh[q]);
                z[q] += f.x + f.y;
            }
            if (!dg) {
#pragma unroll
                for (int n = 0; n < 4; n++) {
                    uint32_t v = csh[n];
                    v = hadd2(v, __shfl_xor_sync(0xffffffffu, v, 4));
                    v = hadd2(v, __shfl_xor_sync(0xffffffffu, v, 8));
                    v = hadd2(v, __shfl_xor_sync(0xffffffffu, v, 16));
                    csh[n] = v;
                }
                if (lane < 4) {
                    float* zj = &g_Z[jblk * 128 + warp_n * 32 + lane * 2];
#pragma unroll
                    for (int n = 0; n < 4; n++) {
                        float2 f = h2_to_f2(csh[n]);
                        atomicAdd(&zj[n * 8 + 0], f.x * ESCALE);
                        atomicAdd(&zj[n * 8 + 1], f.y * ESCALE);
                    }
                }
            }
        }
    }

    // final flush of row sums for cur_ib
#pragma unroll
    for (int q = 0; q < 4; q++) {
        z[q] += __shfl_xor_sync(0xffffffffu, z[q], 1);
        z[q] += __shfl_xor_sync(0xffffffffu, z[q], 2);
    }
    __syncthreads();
    if ((lane & 3) == 0) {
        int g4 = lane >> 2;
#pragma unroll
        for (int m = 0; m < 2; m++)
#pragma unroll
            for (int h = 0; h < 2; h++)
                red[warp_n * 128 + warp_m * 32 + m * 16 + h * 8 + g4] = z[2 * m + h];
    }
    __syncthreads();
    if (t < 128)
        atomicAdd(&g_Z[cur_ib * 128 + t],
                  (red[t] + red[128 + t] + red[256 + t] + red[384 + t]) * ESCALE);
}

// ------------------------- kernel 3: per-sample loss from fp8 rows + last-block final write -------------------------
__global__ void finalize1(const int* __restrict__ labels, float* __restrict__ out) {
    __shared__ float wsum[8];
    const int t = threadIdx.x, lane = t & 31, wid = t >> 5;
    const int b = blockIdx.x * 8 + wid;           // sample 0..4095
    const int cls = labels[b];
    const uint4 u0 = reinterpret_cast<const uint4*>(g_A8 + (size_t)b * DIM)[lane];
    const uint4 u1 = reinterpret_cast<const uint4*>(g_A8 + (size_t)(BATCH + b) * DIM)[lane];
    const float4* srow = reinterpret_cast<const float4*>(g_Ssum) + (size_t)cls * 128;
    float dot0 = 0.f, self0 = 0.f, dot1 = 0.f, self1 = 0.f;
    const uint32_t w0[4] = {u0.x, u0.y, u0.z, u0.w};
    const uint32_t w1[4] = {u1.x, u1.y, u1.z, u1.w};
#pragma unroll
    for (int q = 0; q < 4; q++) {
        float4 s = srow[lane * 4 + q];
        float2 a0l = fp8x2_to_f2(w0[q] & 0xFFFFu);
        float2 a0h = fp8x2_to_f2(w0[q] >> 16);
        float2 a1l = fp8x2_to_f2(w1[q] & 0xFFFFu);
        float2 a1h = fp8x2_to_f2(w1[q] >> 16);
        dot0  += a0l.x * s.x + a0l.y * s.y + a0h.x * s.z + a0h.y * s.w;
        self0 += a0l.x * a0l.x + a0l.y * a0l.y + a0h.x * a0h.x + a0h.y * a0h.y;
        dot1  += a1l.x * s.x + a1l.y * s.y + a1h.x * s.z + a1h.y * s.w;
        self1 += a1l.x * a1l.x + a1l.y * a1l.y + a1h.x * a1h.x + a1h.y * a1h.y;
    }
#pragma unroll
    for (int o = 16; o; o >>= 1) {
        dot0  += __shfl_xor_sync(0xffffffffu, dot0, o);
        self0 += __shfl_xor_sync(0xffffffffu, self0, o);
        dot1  += __shfl_xor_sync(0xffffffffu, dot1, o);
        self1 += __shfl_xor_sync(0xffffffffu, self1, o);
    }
    if (lane == 0) {
        float C = 2.0f * (float)g_cnt[cls] - 1.0f;
        float rC = 1.0f / (C + 1e-8f);
        float l0 = ((dot0 - self0) * INV_T - C * logf(g_Z[b] + 1e-8f)) * rC;
        float l1 = ((dot1 - self1) * INV_T - C * logf(g_Z[BATCH + b] + 1e-8f)) * rC;
        wsum[wid] = l0 + l1;
    }
    __syncthreads();
    if (t == 0) {
        float bs = 0.f;
#pragma unroll
        for (int w = 0; w < 8; w++) bs += wsum[w];
        atomicAdd(&g_sum, bs);
        __threadfence();
        unsigned tk = atomicAdd(&g_done, 1u);
        if (tk == gridDim.x - 1) {
            float s;
            asm volatile("ld.acquire.gpu.f32 %0, [%1];" : "=f"(s) : "l"(&g_sum));
            out[0] = -s / (float)NTOT;
        }
    }
}

// ------------------------- launch -------------------------
extern "C" void kernel_launch(void* const* d_in, const int* in_sizes, int n_in,
                              void* d_out, int out_size) {
    const float* feats = (const float*)d_in[0];
    const int* labels = (const int*)d_in[1];
    (void)in_sizes; (void)n_in; (void)out_size;

    void* p_ssum = nullptr; void* p_cnt = nullptr; void* p_sum = nullptr; void* p_done = nullptr;
    cudaGetSymbolAddress(&p_ssum, g_Ssum);
    cudaGetSymbolAddress(&p_cnt, g_cnt);
    cudaGetSymbolAddress(&p_sum, g_sum);
    cudaGetSymbolAddress(&p_done, g_done);
    cudaMemsetAsync(p_ssum, 0, (size_t)NCLS * DIM * sizeof(float));
    cudaMemsetAsync(p_cnt, 0, NCLS * sizeof(int));
    cudaMemsetAsync(p_sum, 0, sizeof(float));
    cudaMemsetAsync(p_done, 0, sizeof(unsigned));

    cudaFuncSetAttribute(supcon_main, cudaFuncAttributeMaxDynamicSharedMemorySize, SMEM_TOTAL);

    norm_kernel<<<BATCH / 8, 256>>>(feats, labels);
    supcon_main<<<NCTA, 512, SMEM_TOTAL>>>();
    finalize1<<<BATCH / 8, 256>>>(labels, (float*)d_out);
}